// round 7
// baseline (speedup 1.0000x reference)
#include <cuda_runtime.h>

// Problem constants (fixed by the dataset): B=2, N=64, CI=32, CO=32
#define B2 2
#define NP 64
#define CIc 32
#define COc 32

// Scratch (device globals, zero-inited). partials: t=0 ft(=fs row), t=1..3 d-weighted
__device__ float g_part[B2][NP][4][CIc];
__device__ unsigned int g_c1[B2];    // phase-1 arrivals
__device__ unsigned int g_c3[B2];    // completion (for reset)

__global__ void __launch_bounds__(256, 1) pc_fused(
    const float* __restrict__ f,
    const float* __restrict__ geom,
    const float* __restrict__ W,
    const void*  __restrict__ nnp,
    float* __restrict__ out)
{
    int z    = blockIdx.x >> 6;
    int a    = blockIdx.x & 63;      // == c for phase 1, == output row a later
    int tid  = threadIdx.x;
    int lane = tid & 31;
    int w    = tid >> 5;

    __shared__ float gsh[NP][3];
    __shared__ __align__(16) float red[7][CIc];     // 0=ft, 1..3=GFd, 4..6=GFs
    __shared__ __align__(16) float Aa[3][COc], Ab[3][COc], Cst[3][COc];
    __shared__ __align__(16) float UaS[COc];
    __shared__ float shr[8][4][CIc];

    for (int t = tid; t < NP * 3; t += 256)
        gsh[t / 3][t % 3] = geom[z * NP * 3 + t];
    __syncthreads();

    // ---- Phase 1: this block reduces rows (c=a, d=0..63) over d ----------
    const float* base = f + ((size_t)(z * NP + a) * NP) * CIc + lane;
    float a0 = 0.f, a1 = 0.f, a2 = 0.f, a3 = 0.f;
    #pragma unroll
    for (int k = 0; k < 8; k++) {
        int d = w + 8 * k;
        float v = base[d * CIc];                    // coalesced
        a0 += v;
        a1 += v * gsh[d][0];
        a2 += v * gsh[d][1];
        a3 += v * gsh[d][2];
    }
    shr[w][0][lane] = a0; shr[w][1][lane] = a1;
    shr[w][2][lane] = a2; shr[w][3][lane] = a3;
    __syncthreads();
    if (tid < 128) {
        int t = tid >> 5;
        float s = 0.f;
        #pragma unroll
        for (int k = 0; k < 8; k++) s += shr[k][t][lane];
        g_part[z][a][t][lane] = s;
    }
    __syncthreads();

    // ---- Grid barrier (per z): arrive, tight poll, acquire ---------------
    if (tid == 0) {
        __threadfence();
        atomicAdd(&g_c1[z], 1u);
        volatile unsigned int* p = &g_c1[z];
        while (*p < (unsigned)NP) { }               // tight spin, L2 poll
        __threadfence();
    }
    __syncthreads();

    // ---- All blocks: re-reduce partials from L2 --------------------------
    if (tid < 224) {
        int t = tid >> 5;                           // 0..6
        float acc = 0.f;
        if (t == 0) {
            #pragma unroll 8
            for (int c = 0; c < NP; c++) acc += g_part[z][c][0][lane];
        } else if (t < 4) {
            #pragma unroll 8
            for (int c = 0; c < NP; c++) acc += g_part[z][c][t][lane];
        } else {
            int x = t - 4;
            #pragma unroll 8
            for (int c = 0; c < NP; c++)
                acc += gsh[c][x] * g_part[z][c][0][lane];
        }
        red[t][lane] = acc;
    }
    __syncthreads();

    // ---- Per-thread (x,i) dot products over j (float4, no shuffles) ------
    if (tid < 96) {
        int x = tid >> 5, i = tid & 31;
        const float4* Wb = reinterpret_cast<const float4*>(
            W + (size_t)x * (6 * COc * CIc) + i * CIc);
        const float4* ftv = reinterpret_cast<const float4*>(&red[0][0]);
        const float4* gdv = reinterpret_cast<const float4*>(&red[1 + x][0]);
        const float4* gsv = reinterpret_cast<const float4*>(&red[4 + x][0]);
        float aa = 0.f, ab = 0.f, cc = 0.f;
        #pragma unroll
        for (int q = 0; q < 8; q++) {
            float4 w1 = Wb[0 * 256 + q];
            float4 w2 = Wb[1 * 256 + q];
            float4 w3 = Wb[2 * 256 + q];
            float4 w4 = Wb[3 * 256 + q];
            float4 w5 = Wb[4 * 256 + q];
            float4 w6 = Wb[5 * 256 + q];
            float4 ft4 = ftv[q], gs4 = gsv[q], gd4 = gdv[q];
            aa += (w1.x + w2.x + w3.x) * ft4.x + (w1.y + w2.y + w3.y) * ft4.y
                + (w1.z + w2.z + w3.z) * ft4.z + (w1.w + w2.w + w3.w) * ft4.w;
            ab += (w1.x - w4.x - w5.x) * ft4.x + (w1.y - w4.y - w5.y) * ft4.y
                + (w1.z - w4.z - w5.z) * ft4.z + (w1.w - w4.w - w5.w) * ft4.w;
            cc += (w2.x + w4.x) * gs4.x + (w3.x + w5.x) * gd4.x + w6.x * (gd4.x - gs4.x)
                + (w2.y + w4.y) * gs4.y + (w3.y + w5.y) * gd4.y + w6.y * (gd4.y - gs4.y)
                + (w2.z + w4.z) * gs4.z + (w3.z + w5.z) * gd4.z + w6.z * (gd4.z - gs4.z)
                + (w2.w + w4.w) * gs4.w + (w3.w + w5.w) * gd4.w + w6.w * (gd4.w - gs4.w);
        }
        Aa[x][i] = aa; Ab[x][i] = ab; Cst[x][i] = cc;
    }
    __syncthreads();

    // n_norm: tolerate int32 or float32 encoding
    int   iv = *(const int*)nnp;
    float nn = (iv >= 1 && iv <= (1 << 20)) ? (float)iv : *(const float*)nnp;
    float s  = rsqrtf(6.0f * nn * nn);

    if (tid < COc) {
        float cv = s * (Cst[0][tid] + Cst[1][tid] + Cst[2][tid]);
        float g0 = gsh[a][0], g1 = gsh[a][1], g2 = gsh[a][2];
        UaS[tid] = cv - s * (g0 * Aa[0][tid] + g1 * Aa[1][tid] + g2 * Aa[2][tid]);
        Ab[0][tid] *= s; Ab[1][tid] *= s; Ab[2][tid] *= s;   // pre-scale
    }
    __syncthreads();

    // ---- Output: out[z,a,b,i] = Ua[a,i] + <g_b, Ab[:,i]>, float4 stores --
    {
        const float4* ua4  = reinterpret_cast<const float4*>(UaS);
        const float4* ab04 = reinterpret_cast<const float4*>(&Ab[0][0]);
        const float4* ab14 = reinterpret_cast<const float4*>(&Ab[1][0]);
        const float4* ab24 = reinterpret_cast<const float4*>(&Ab[2][0]);
        float4* o = reinterpret_cast<float4*>(
            out + ((size_t)(z * NP + a) * NP) * COc);
        #pragma unroll
        for (int slot = tid; slot < NP * 8; slot += 256) {
            int b = slot >> 3, q = slot & 7;
            float gb0 = gsh[b][0], gb1 = gsh[b][1], gb2 = gsh[b][2];
            float4 u = ua4[q], v0 = ab04[q], v1 = ab14[q], v2 = ab24[q];
            float4 r;
            r.x = u.x + gb0 * v0.x + gb1 * v1.x + gb2 * v2.x;
            r.y = u.y + gb0 * v0.y + gb1 * v1.y + gb2 * v2.y;
            r.z = u.z + gb0 * v0.z + gb1 * v1.z + gb2 * v2.z;
            r.w = u.w + gb0 * v0.w + gb1 * v1.w + gb2 * v2.w;
            o[slot] = r;
        }
    }

    // ---- Reset barrier state for next graph replay -----------------------
    __syncthreads();
    if (tid == 0) {
        unsigned int v = atomicAdd(&g_c3[z], 1u);
        if (v == (unsigned)(NP - 1)) {              // last block of this z
            atomicExch(&g_c1[z], 0u);
            atomicExch(&g_c3[z], 0u);
        }
    }
}

// ---------------------------------------------------------------------------
extern "C" void kernel_launch(void* const* d_in, const int* in_sizes, int n_in,
                              void* d_out, int out_size) {
    const float* features = (const float*)d_in[0]; // [2,64,64,32]
    const float* geometry = (const float*)d_in[1]; // [2,64,3]
    const float* W        = (const float*)d_in[2]; // [3,6144]
    const void*  n_norm   = d_in[3];               // scalar
    float* out = (float*)d_out;                    // [2,64,64,32]

    pc_fused<<<B2 * NP, 256>>>(features, geometry, W, n_norm, out);
}

// round 8
// speedup vs baseline: 1.3583x; 1.3583x over previous
#include <cuda_runtime.h>

// Problem constants (fixed by the dataset): B=2, N=64, CI=32, CO=32
#define B2 2
#define NP 64
#define CIc 32
#define COc 32
#define P16 16                      // k1 blocks per z
#define ROWS_PB (NP * NP / P16)     // 256 rows per block

// Scratch: per-block partials [z][p][t][j]; t: 0=ft, 1..3=GFs(x), 4..6=GFd(x)
__device__ float g_part[B2][P16][7][CIc];

// ---------------------------------------------------------------------------
// K1: streaming weighted reduction. Row r = c*64 + d, weights {1, g[c], g[d]}.
// grid = 32 (2 z * 16), block = 256 (lane = channel j)
// ---------------------------------------------------------------------------
__global__ void __launch_bounds__(256, 1) pc_k1(const float* __restrict__ f,
                                                const float* __restrict__ geom) {
    // Let the dependent kernel start its prologue immediately.
    asm volatile("griddepcontrol.launch_dependents;");

    int z   = blockIdx.x >> 4;
    int blk = blockIdx.x & 15;
    int j   = threadIdx.x & 31;
    int w   = threadIdx.x >> 5;

    __shared__ float gsh[NP][3];
    for (int t = threadIdx.x; t < NP * 3; t += 256)
        gsh[t / 3][t % 3] = geom[z * NP * 3 + t];
    __syncthreads();

    int r0 = blk * ROWS_PB;
    const float* base = f + ((size_t)z * NP * NP + r0) * CIc + j;

    float a0 = 0.f, a1 = 0.f, a2 = 0.f, a3 = 0.f, a4 = 0.f, a5 = 0.f, a6 = 0.f;
    #pragma unroll
    for (int k = 0; k < ROWS_PB / 8; k++) {       // 32 independent loads
        int rr = w + 8 * k;                        // 0..255
        float v = base[rr * CIc];                  // coalesced
        int c = (r0 + rr) >> 6, d = rr & 63;
        a0 += v;
        a1 += v * gsh[c][0];
        a2 += v * gsh[c][1];
        a3 += v * gsh[c][2];
        a4 += v * gsh[d][0];
        a5 += v * gsh[d][1];
        a6 += v * gsh[d][2];
    }

    __shared__ float sh[8][7][CIc];
    sh[w][0][j] = a0; sh[w][1][j] = a1; sh[w][2][j] = a2; sh[w][3][j] = a3;
    sh[w][4][j] = a4; sh[w][5][j] = a5; sh[w][6][j] = a6;
    __syncthreads();

    if (threadIdx.x < 224) {
        int t  = threadIdx.x >> 5;                 // 0..6
        int jj = threadIdx.x & 31;
        float s = 0.f;
        #pragma unroll
        for (int k = 0; k < 8; k++) s += sh[k][t][jj];
        g_part[z][blk][t][jj] = s;
    }
}

// ---------------------------------------------------------------------------
// K2: one block per (z, a). Prologue (geometry) before griddepcontrol.wait,
// then 16-partial re-reduce, per-thread (x,i) float4 dots, float4 epilogue.
// grid = 128, block = 256
// ---------------------------------------------------------------------------
__global__ void __launch_bounds__(256, 1) pc_k2(const float* __restrict__ geom,
                                                const float* __restrict__ W,
                                                const void*  __restrict__ nnp,
                                                float* __restrict__ out) {
    int z    = blockIdx.x >> 6;
    int a    = blockIdx.x & 63;
    int tid  = threadIdx.x;
    int lane = tid & 31;
    int w    = tid >> 5;

    __shared__ float gsh[NP][3];
    __shared__ __align__(16) float red[7][CIc];    // ft, GFs[3], GFd[3]
    __shared__ __align__(16) float Aa[3][COc], Ab[3][COc], Cst[3][COc];
    __shared__ __align__(16) float UaS[COc];

    // ---- Prologue (overlapped with k1 via PDL) ----
    for (int t = tid; t < NP * 3; t += 256)
        gsh[t / 3][t % 3] = geom[z * NP * 3 + t];

    // n_norm: tolerate int32 or float32 encoding
    int   iv = *(const int*)nnp;
    float nn = (iv >= 1 && iv <= (1 << 20)) ? (float)iv : *(const float*)nnp;
    float s  = rsqrtf(6.0f * nn * nn);

    // ---- Wait for k1's grid (memory visible afterwards) ----
    asm volatile("griddepcontrol.wait;");
    __syncthreads();

    if (tid < 224) {
        int t = tid >> 5;                          // 0..6
        float acc = 0.f;
        #pragma unroll
        for (int p = 0; p < P16; p++)              // 16 independent loads
            acc += g_part[z][p][t][lane];
        red[t][lane] = acc;
    }
    __syncthreads();

    // Per-thread (x,i): 32-length dot products, float4, no shuffles
    if (tid < 96) {
        int x = tid >> 5, i = tid & 31;
        const float4* Wb = reinterpret_cast<const float4*>(
            W + (size_t)x * (6 * COc * CIc) + i * CIc);
        const float4* ftv = reinterpret_cast<const float4*>(&red[0][0]);
        const float4* gsv = reinterpret_cast<const float4*>(&red[1 + x][0]);
        const float4* gdv = reinterpret_cast<const float4*>(&red[4 + x][0]);
        float aa = 0.f, ab = 0.f, cc = 0.f;
        #pragma unroll
        for (int q = 0; q < 8; q++) {
            float4 w1 = Wb[0 * 256 + q];
            float4 w2 = Wb[1 * 256 + q];
            float4 w3 = Wb[2 * 256 + q];
            float4 w4 = Wb[3 * 256 + q];
            float4 w5 = Wb[4 * 256 + q];
            float4 w6 = Wb[5 * 256 + q];
            float4 ft4 = ftv[q], gs4 = gsv[q], gd4 = gdv[q];
            aa += (w1.x + w2.x + w3.x) * ft4.x + (w1.y + w2.y + w3.y) * ft4.y
                + (w1.z + w2.z + w3.z) * ft4.z + (w1.w + w2.w + w3.w) * ft4.w;
            ab += (w1.x - w4.x - w5.x) * ft4.x + (w1.y - w4.y - w5.y) * ft4.y
                + (w1.z - w4.z - w5.z) * ft4.z + (w1.w - w4.w - w5.w) * ft4.w;
            cc += (w2.x + w4.x) * gs4.x + (w3.x + w5.x) * gd4.x + w6.x * (gd4.x - gs4.x)
                + (w2.y + w4.y) * gs4.y + (w3.y + w5.y) * gd4.y + w6.y * (gd4.y - gs4.y)
                + (w2.z + w4.z) * gs4.z + (w3.z + w5.z) * gd4.z + w6.z * (gd4.z - gs4.z)
                + (w2.w + w4.w) * gs4.w + (w3.w + w5.w) * gd4.w + w6.w * (gd4.w - gs4.w);
        }
        Aa[x][i] = aa; Ab[x][i] = ab; Cst[x][i] = cc;
    }
    __syncthreads();

    if (tid < COc) {
        float cv = s * (Cst[0][tid] + Cst[1][tid] + Cst[2][tid]);
        float g0 = gsh[a][0], g1 = gsh[a][1], g2 = gsh[a][2];
        UaS[tid] = cv - s * (g0 * Aa[0][tid] + g1 * Aa[1][tid] + g2 * Aa[2][tid]);
        Ab[0][tid] *= s; Ab[1][tid] *= s; Ab[2][tid] *= s;   // pre-scale
    }
    __syncthreads();

    // out[z,a,b,i] = Ua[a,i] + <g_b, Ab[:,i]>, float4 stores
    const float4* ua4  = reinterpret_cast<const float4*>(UaS);
    const float4* ab04 = reinterpret_cast<const float4*>(&Ab[0][0]);
    const float4* ab14 = reinterpret_cast<const float4*>(&Ab[1][0]);
    const float4* ab24 = reinterpret_cast<const float4*>(&Ab[2][0]);
    float4* o = reinterpret_cast<float4*>(out + ((size_t)(z * NP + a) * NP) * COc);
    #pragma unroll
    for (int slot = tid; slot < NP * 8; slot += 256) {
        int b = slot >> 3, q = slot & 7;
        float gb0 = gsh[b][0], gb1 = gsh[b][1], gb2 = gsh[b][2];
        float4 u = ua4[q], v0 = ab04[q], v1 = ab14[q], v2 = ab24[q];
        float4 r;
        r.x = u.x + gb0 * v0.x + gb1 * v1.x + gb2 * v2.x;
        r.y = u.y + gb0 * v0.y + gb1 * v1.y + gb2 * v2.y;
        r.z = u.z + gb0 * v0.z + gb1 * v1.z + gb2 * v2.z;
        r.w = u.w + gb0 * v0.w + gb1 * v1.w + gb2 * v2.w;
        o[slot] = r;
    }
}

// ---------------------------------------------------------------------------
extern "C" void kernel_launch(void* const* d_in, const int* in_sizes, int n_in,
                              void* d_out, int out_size) {
    const float* features = (const float*)d_in[0]; // [2,64,64,32]
    const float* geometry = (const float*)d_in[1]; // [2,64,3]
    const float* W        = (const float*)d_in[2]; // [3,6144]
    const void*  n_norm   = d_in[3];               // scalar
    float* out = (float*)d_out;                    // [2,64,64,32]

    pc_k1<<<B2 * P16, 256>>>(features, geometry);

    // k2 with programmatic dependent launch (overlap prologue with k1)
    cudaLaunchConfig_t cfg = {};
    cfg.gridDim  = dim3(B2 * NP, 1, 1);
    cfg.blockDim = dim3(256, 1, 1);
    cfg.stream   = 0;
    cudaLaunchAttribute attr[1];
    attr[0].id = cudaLaunchAttributeProgrammaticStreamSerialization;
    attr[0].val.programmaticStreamSerializationAllowed = 1;
    cfg.attrs    = attr;
    cfg.numAttrs = 1;
    cudaError_t e = cudaLaunchKernelEx(&cfg, pc_k2, geometry, W, n_norm,
                                       (float*)d_out);
    if (e != cudaSuccess) {
        // Fallback: plain launch (griddepcontrol.wait is a no-op then)
        pc_k2<<<B2 * NP, 256>>>(geometry, W, n_norm, (float*)d_out);
    }
}